// round 17
// baseline (speedup 1.0000x reference)
#include <cuda_runtime.h>
#include <cstdint>
#include <math.h>

// ---------------------------------------------------------------------------
// PreferencePredictor (sm_100, mma.sync m16n8k16 fp16) — round 17
//
//   l      = llm @ Wl.T (+bl in epilogue)     [M,256]  GEMM, BM=128 BN=256
//   s_h    = dbs_h + dWs_h . (acc+bl)         -> a_h = sigmoid(s_h)
//   att    = base + sum_h a_h * c_h           [256]
//   logit  = relu(att)@Wo[:256] + relu(l)@Wo[256:] + bo
//
// vs R16 (best, 209.7us): ks-granular fragment DOUBLE-BUFFER with textually
// interleaved loads+mma, so the LSU (crossbar) phase and tensor phase overlap
// instead of serializing. mma order unchanged -> bitwise-identical output.
// ---------------------------------------------------------------------------

#define KTILES 24
#define ASTRIDE 40                          // floats per A row (conflict-free LDS.64)
#define A_FLOATS (128*ASTRIDE)              // 5120
#define B_U32    4096                       // 16 kpairs x 256 n half2
#define STAGE_FLOATS (A_FLOATS + B_U32)     // 9216
#define NSTAGE 3
#define EPI_F (NSTAGE*STAGE_FLOATS)         // 27648

#define EPI_BASE 0
#define EPI_CC   256
#define EPI_WOA  1280
#define EPI_WOL  1536
#define EPI_BL   1792
#define EPI_DWS  2048
#define EPI_DBS  3072
#define EPI_RED  3080                        // [128][4][5]
#define EPI_AW   5640                        // [128][4]
#define EPI_PL   6152                        // [128]
#define EPI_RED2 6280                        // [128][2]
#define EPI_TOT  6536
#define SMEM_BYTES ((EPI_F + EPI_TOT)*4)

// ---- persistent scratch ----
__device__ __align__(256) float g_u[256], g_qv[256];
__device__ __align__(256) float g_k[512], g_v[512];
__device__ __align__(256) float g_Ws[8*256], g_bs[8];
__device__ __align__(256) float g_base[256], g_cc[4*256];
__device__ __align__(256) uint32_t g_Wh[24*B_U32];  // half2-packed swizzled Wl

// ---- helpers ----
__device__ __forceinline__ uint32_t packh2(float lo, float hi){
    uint32_t r; asm("cvt.rn.f16x2.f32 %0, %1, %2;" : "=r"(r) : "f"(hi), "f"(lo)); return r;
}
__device__ __forceinline__ void cpa16(uint32_t dst, const void* src){
    asm volatile("cp.async.cg.shared.global [%0], [%1], 16;" :: "r"(dst), "l"(src));
}
__device__ __forceinline__ void cp_commit(){ asm volatile("cp.async.commit_group;" ::: "memory"); }
__device__ __forceinline__ void cp_wait1(){ asm volatile("cp.async.wait_group 1;" ::: "memory"); }

__device__ __forceinline__ void mma_f16(float&c0,float&c1,float&c2,float&c3,
                                        uint32_t a0,uint32_t a1,uint32_t a2,uint32_t a3,
                                        uint32_t b0,uint32_t b1){
    asm volatile(
        "mma.sync.aligned.m16n8k16.row.col.f32.f16.f16.f32 "
        "{%0,%1,%2,%3},{%4,%5,%6,%7},{%8,%9},{%0,%1,%2,%3};"
        : "+f"(c0),"+f"(c1),"+f"(c2),"+f"(c3)
        : "r"(a0),"r"(a1),"r"(a2),"r"(a3),"r"(b0),"r"(b1));
}
__device__ __forceinline__ float wreduce(float s){
    #pragma unroll
    for (int o=16;o;o>>=1) s += __shfl_xor_sync(0xffffffffu, s, o);
    return s;
}

// fragment loaders (register-destination; textual position controls issue order)
__device__ __forceinline__ void load_bf(uint32_t (&bfk)[2][8], const uint32_t* Bs,
                                        int ks, int j, int qq, int wn, int bsw){
    #pragma unroll
    for (int r=0;r<2;r++){
        const int kp = ks*8 + j + r*4;
        const uint32_t* cell = Bs + (kp*8+qq)*32;
        #pragma unroll
        for (int c=0;c<2;c++){
            const int chunk = (wn*2 + c) ^ bsw;
            const uint4 v = *(const uint4*)(cell + chunk*4);
            bfk[r][c*4+0]=v.x; bfk[r][c*4+1]=v.y;
            bfk[r][c*4+2]=v.z; bfk[r][c*4+3]=v.w;
        }
    }
}
__device__ __forceinline__ void load_af_t(uint32_t (&aft)[4], const float* As,
                                          int ks, int t, int j, int qq, int wm){
    const int k0 = ks*16 + 2*j;
    const int row = wm*64 + t*16 + qq;
    float2 p0 = *(const float2*)(As + row*ASTRIDE + k0);
    float2 p1 = *(const float2*)(As + (row+8)*ASTRIDE + k0);
    float2 p2 = *(const float2*)(As + row*ASTRIDE + k0 + 8);
    float2 p3 = *(const float2*)(As + (row+8)*ASTRIDE + k0 + 8);
    aft[0]=packh2(p0.x,p0.y); aft[1]=packh2(p1.x,p1.y);
    aft[2]=packh2(p2.x,p2.y); aft[3]=packh2(p3.x,p3.y);
}

// ---- prep 1: u, qv ----
__global__ void __launch_bounds__(256) prep_uq(
    const float* __restrict__ user, const float* __restrict__ query,
    const float* __restrict__ Wu, const float* __restrict__ bu,
    const float* __restrict__ Wq, const float* __restrict__ bq){
    int w = blockIdx.x*8 + (threadIdx.x>>5);
    int lane = threadIdx.x&31;
    const float *x, *W, *b; float* out; int i;
    if (w < 256){ x=user;  W=Wu; b=bu; out=g_u;  i=w; }
    else        { x=query; W=Wq; b=bq; out=g_qv; i=w-256; }
    float s=0.f;
    #pragma unroll
    for (int t=0;t<24;t++){ int jj=lane+t*32; s += x[jj]*W[i*768+jj]; }
    s = wreduce(s);
    if (!lane) out[i] = s + b[i];
}

// ---- prep 2: k, v ----
__global__ void __launch_bounds__(256) prep_kv(
    const float* __restrict__ ipw, const float* __restrict__ ipb){
    int w = blockIdx.x*8 + (threadIdx.x>>5);   // 0..1023
    int lane = threadIdx.x&31;
    int i = w & 255;
    int which = w >> 8;
    int c = which & 1;
    int kv = which >> 1;
    const float* ctx = c ? g_qv : g_u;
    int row = 256 + kv*256 + i;
    float s=0.f;
    #pragma unroll
    for (int t=0;t<8;t++){ int jj=lane+t*32; s += ctx[jj]*ipw[row*256+jj]; }
    s = wreduce(s);
    if (!lane){
        float val = s + ipb[row];
        if (kv) g_v[c*256+i] = val; else g_k[c*256+i] = val;
    }
}

// ---- prep 3 (merged): blocks 0..416 = W_s/b_s/base/c ; blocks 417..440 = Wl pack
__global__ void __launch_bounds__(256) prep_sb(
    const float* __restrict__ ipw, const float* __restrict__ ipb,
    const float* __restrict__ opw, const float* __restrict__ opb,
    const float* __restrict__ Wl){
    if (blockIdx.x >= 417){
        int kt = blockIdx.x - 417;    // 0..23
        int n  = threadIdx.x;         // 0..255
        int qq = n & 7, ntg = n >> 3;
        uint32_t* dst = g_Wh + kt*B_U32;
        #pragma unroll
        for (int kp=0; kp<16; kp++){
            float lo = Wl[n*768 + kt*32 + kp*2];
            float hi = Wl[n*768 + kt*32 + kp*2 + 1];
            int s = (qq&1)*4 + (kp&3);
            int chunk = (ntg>>2) ^ s;
            dst[(kp*8+qq)*32 + chunk*4 + (ntg&3)] = packh2(lo, hi);
        }
        return;
    }
    int w = blockIdx.x*8 + (threadIdx.x>>5);
    int lane = threadIdx.x&31;
    float s=0.f;
    if (w < 256){
        int i=w;
        #pragma unroll
        for (int t=0;t<8;t++){ int jj=lane+t*32; s += g_v[256+jj]*opw[i*256+jj]; }
        s = wreduce(s);
        if (!lane) g_base[i] = s + opb[i];
    } else if (w < 1280){
        int o=w-256, h=o>>8, i=o&255;
        #pragma unroll
        for (int t=0;t<2;t++){ int d=lane+t*32; int jj=h*64+d;
            s += (g_v[jj]-g_v[256+jj])*opw[i*256+jj]; }
        s = wreduce(s);
        if (!lane) g_cc[h*256+i] = s;
    } else if (w < 3328){
        int o=w-1280, r=o>>8, i=o&255, h=r>>1, kidx=r&1;
        #pragma unroll
        for (int t=0;t<2;t++){ int d=lane+t*32;
            s += g_k[kidx*256+h*64+d]*ipw[(h*64+d)*256+i]; }
        s = wreduce(s);
        if (!lane) g_Ws[r*256+i] = 0.125f*s;
    } else if (w < 3336){
        int r=w-3328, h=r>>1, kidx=r&1;
        #pragma unroll
        for (int t=0;t<2;t++){ int d=lane+t*32;
            s += ipb[h*64+d]*g_k[kidx*256+h*64+d]; }
        s = wreduce(s);
        if (!lane) g_bs[r] = 0.125f*s;
    }
}

// ---- main GEMM + fused epilogue (256 threads, 2x4 warp grid) ----
__global__ void __launch_bounds__(256,1) main_gemm(
    const float* __restrict__ llm, const float* __restrict__ Wo,
    const float* __restrict__ bo, const float* __restrict__ bl,
    float* __restrict__ out){
    extern __shared__ float sm[];
    const int tid = threadIdx.x, lane = tid&31, warp = tid>>5;
    const int j = lane&3, qq = lane>>2;
    const int wm = warp&1, wn = warp>>1;           // 2 x 4 warp grid
    const uint32_t smu = (uint32_t)__cvta_generic_to_shared(sm);
    float* epi = sm + EPI_F;

    auto issue = [&](int kt){
        int slot = kt % NSTAGE;
        uint32_t sb = smu + (uint32_t)(slot*STAGE_FLOATS)*4u;
        const float* Asrc = llm + (size_t)blockIdx.x*(128*768) + kt*32;
        #pragma unroll
        for (int ch=tid; ch<1024; ch+=256){
            int row = ch>>3, u = ch&7;
            cpa16(sb + (uint32_t)(row*ASTRIDE + u*4)*4u, Asrc + (size_t)row*768 + u*4);
        }
        const uint32_t* Bsrc = g_Wh + kt*B_U32;
        uint32_t bb = sb + (uint32_t)A_FLOATS*4u;
        #pragma unroll
        for (int ch=tid; ch<1024; ch+=256)
            cpa16(bb + (uint32_t)ch*16u, Bsrc + ch*4);
    };

    issue(0); cp_commit();
    issue(1); cp_commit();

    // stage epilogue constants (overlaps async loads); dWs/dbs formed inline
    {
        int i = tid;
        epi[EPI_BASE+i] = g_base[i];
        #pragma unroll
        for (int h=0;h<4;h++) epi[EPI_CC + h*256 + i] = g_cc[h*256+i];
        epi[EPI_WOA+i] = __ldg(Wo+i);
        epi[EPI_WOL+i] = __ldg(Wo+256+i);
        epi[EPI_BL +i] = __ldg(bl+i);
        #pragma unroll
        for (int h=0;h<4;h++)
            epi[EPI_DWS + h*256 + i] = g_Ws[(2*h)*256+i] - g_Ws[(2*h+1)*256+i];
        if (i<4) epi[EPI_DBS+i] = g_bs[2*i] - g_bs[2*i+1];
    }

    float acc[4][8][4];
    #pragma unroll
    for (int t=0;t<4;t++)
        #pragma unroll
        for (int nt=0;nt<8;nt++)
            #pragma unroll
            for (int c=0;c<4;c++) acc[t][nt][c]=0.f;

    const int bsw = (qq&1)*4 + j;          // B chunk swizzle key

    // fragment double buffers (ks granularity)
    uint32_t bfb[2][2][8];
    uint32_t afb[2][4][4];

    // prologue: tile 0 resident, load (0, ks=0) into buffer 0
    cp_wait1();
    __syncthreads();
    {
        const float* As0 = sm;
        const uint32_t* Bs0 = (const uint32_t*)(sm + A_FLOATS);
        load_bf(bfb[0], Bs0, 0, j, qq, wn, bsw);
        #pragma unroll
        for (int t=0;t<4;t++) load_af_t(afb[0][t], As0, 0, t, j, qq, wm);
    }

    #pragma unroll 3
    for (int kt=0; kt<KTILES; kt++){
        const int slot = kt % NSTAGE;   // compile-time under unroll-by-3
        const float* As = sm + slot*STAGE_FLOATS;
        const uint32_t* Bs = (const uint32_t*)(As + A_FLOATS);

        // ---- step A: load (kt, ks=1)->buf1 interleaved with mma(buf0) ----
        load_bf(bfb[1], Bs, 1, j, qq, wn, bsw);
        #pragma unroll
        for (int t=0;t<4;t++){
            load_af_t(afb[1][t], As, 1, t, j, qq, wm);
            #pragma unroll
            for (int nt=0;nt<8;nt++)
                mma_f16(acc[t][nt][0],acc[t][nt][1],acc[t][nt][2],acc[t][nt][3],
                        afb[0][t][0],afb[0][t][1],afb[0][t][2],afb[0][t][3],
                        bfb[0][0][nt], bfb[0][1][nt]);
        }

        // ---- step B: boundary, then load (kt+1, ks=0)->buf0 || mma(buf1) ----
        if (kt+2 < KTILES) issue(kt+2);
        cp_commit();             // always commit (keeps group ledger constant)
        cp_wait1();              // tile kt+1 resident (kt+2 in flight)
        __syncthreads();         // WAR fence for slot (kt+2)%3 + visibility of kt+1

        if (kt+1 < KTILES){
            const int ns = (kt+1) % NSTAGE;
            const float* As2 = sm + ns*STAGE_FLOATS;
            const uint32_t* Bs2 = (const uint32_t*)(As2 + A_FLOATS);
            load_bf(bfb[0], Bs2, 0, j, qq, wn, bsw);
            #pragma unroll
            for (int t=0;t<4;t++){
                load_af_t(afb[0][t], As2, 0, t, j, qq, wm);
                #pragma unroll
                for (int nt=0;nt<8;nt++)
                    mma_f16(acc[t][nt][0],acc[t][nt][1],acc[t][nt][2],acc[t][nt][3],
                            afb[1][t][0],afb[1][t][1],afb[1][t][2],afb[1][t][3],
                            bfb[1][0][nt], bfb[1][1][nt]);
            }
        } else {
            #pragma unroll
            for (int t=0;t<4;t++)
                #pragma unroll
                for (int nt=0;nt<8;nt++)
                    mma_f16(acc[t][nt][0],acc[t][nt][1],acc[t][nt][2],acc[t][nt][3],
                            afb[1][t][0],afb[1][t][1],afb[1][t][2],afb[1][t][3],
                            bfb[1][0][nt], bfb[1][1][nt]);
        }
    }
    __syncthreads();

    // ---- epilogue phase A: per-thread partials over owned cols ----
    // score accumulated over lv = acc + bl  (absorbs dWs.bl constant)
    float pl[4][2];
    float sh[4][2][4];
    #pragma unroll
    for (int t=0;t<4;t++)
        #pragma unroll
        for (int hf=0;hf<2;hf++){
            pl[t][hf]=0.f;
            #pragma unroll
            for (int h=0;h<4;h++) sh[t][hf][h]=0.f;
        }
    #pragma unroll
    for (int nt=0;nt<8;nt++){
        #pragma unroll
        for (int cb=0;cb<2;cb++){
            const int col = wn*64 + nt*8 + 2*j + cb;
            const float blv = epi[EPI_BL+col];
            const float wol = epi[EPI_WOL+col];
            const float w0 = epi[EPI_DWS+col];
            const float w1 = epi[EPI_DWS+256+col];
            const float w2 = epi[EPI_DWS+512+col];
            const float w3 = epi[EPI_DWS+768+col];
            #pragma unroll
            for (int t=0;t<4;t++)
                #pragma unroll
                for (int hf=0;hf<2;hf++){
                    float lv = acc[t][nt][hf*2+cb] + blv;
                    pl[t][hf] += fmaxf(lv,0.f)*wol;
                    sh[t][hf][0] += w0*lv;
                    sh[t][hf][1] += w1*lv;
                    sh[t][hf][2] += w2*lv;
                    sh[t][hf][3] += w3*lv;
                }
        }
    }
    #pragma unroll
    for (int t=0;t<4;t++)
        #pragma unroll
        for (int hf=0;hf<2;hf++){
            float v4 = pl[t][hf];
            v4 += __shfl_xor_sync(0xffffffffu, v4, 1);
            v4 += __shfl_xor_sync(0xffffffffu, v4, 2);
            float vh[4];
            #pragma unroll
            for (int h=0;h<4;h++){
                float v = sh[t][hf][h];
                v += __shfl_xor_sync(0xffffffffu, v, 1);
                v += __shfl_xor_sync(0xffffffffu, v, 2);
                vh[h]=v;
            }
            if (j==0){
                int row = wm*64 + t*16 + qq + hf*8;
                float* rp = epi + EPI_RED + (row*4+wn)*5;
                rp[0]=vh[0]; rp[1]=vh[1]; rp[2]=vh[2]; rp[3]=vh[3]; rp[4]=v4;
            }
        }
    __syncthreads();

    // ---- phase B: per-row scores + sigmoid ----
    if (tid < 128){
        int row = tid;
        float s0=epi[EPI_DBS+0], s1=epi[EPI_DBS+1], s2=epi[EPI_DBS+2], s3=epi[EPI_DBS+3];
        float p=0.f;
        #pragma unroll
        for (int w=0;w<4;w++){
            float* rp = epi + EPI_RED + (row*4+w)*5;
            s0+=rp[0]; s1+=rp[1]; s2+=rp[2]; s3+=rp[3]; p+=rp[4];
        }
        epi[EPI_AW+row*4+0] = 1.f/(1.f+expf(-s0));
        epi[EPI_AW+row*4+1] = 1.f/(1.f+expf(-s1));
        epi[EPI_AW+row*4+2] = 1.f/(1.f+expf(-s2));
        epi[EPI_AW+row*4+3] = 1.f/(1.f+expf(-s3));
        epi[EPI_PL+row] = p;
    }
    __syncthreads();

    // ---- phase C: attention dot, 2 threads per row ----
    {
        int row = tid & 127, hf = tid >> 7;
        float a0=epi[EPI_AW+row*4+0], a1=epi[EPI_AW+row*4+1],
              a2=epi[EPI_AW+row*4+2], a3=epi[EPI_AW+row*4+3];
        float p2=0.f;
        #pragma unroll 8
        for (int d=hf*128; d<hf*128+128; d++){
            float att = epi[EPI_BASE+d] + a0*epi[EPI_CC+d] + a1*epi[EPI_CC+256+d]
                      + a2*epi[EPI_CC+512+d] + a3*epi[EPI_CC+768+d];
            p2 += fmaxf(att,0.f)*epi[EPI_WOA+d];
        }
        epi[EPI_RED2 + row*2 + hf] = p2;
    }
    __syncthreads();

    if (tid < 128){
        out[blockIdx.x*128 + tid] = epi[EPI_PL+tid] + epi[EPI_RED2+tid*2]
                                  + epi[EPI_RED2+tid*2+1] + __ldg(bo);
    }
}

// ---------------------------------------------------------------------------
extern "C" void kernel_launch(void* const* d_in, const int* in_sizes, int n_in,
                              void* d_out, int out_size){
    const float* user  = (const float*)d_in[0];
    const float* query = (const float*)d_in[1];
    const float* llm   = (const float*)d_in[2];
    const float* Wu    = (const float*)d_in[3];
    const float* bu    = (const float*)d_in[4];
    const float* Wq    = (const float*)d_in[5];
    const float* bq    = (const float*)d_in[6];
    const float* Wl    = (const float*)d_in[7];
    const float* bl    = (const float*)d_in[8];
    const float* ipw   = (const float*)d_in[9];
    const float* ipb   = (const float*)d_in[10];
    const float* opw   = (const float*)d_in[11];
    const float* opb   = (const float*)d_in[12];
    const float* Wo    = (const float*)d_in[13];
    const float* bo    = (const float*)d_in[14];
    float* out = (float*)d_out;

    int M = in_sizes[2] / 768;

    cudaFuncSetAttribute(main_gemm, cudaFuncAttributeMaxDynamicSharedMemorySize, SMEM_BYTES);

    prep_uq <<<64, 256>>>(user, query, Wu, bu, Wq, bq);
    prep_kv <<<128,256>>>(ipw, ipb);
    prep_sb <<<441,256>>>(ipw, ipb, opw, opb, Wl);
    main_gemm <<<M/128, 256, SMEM_BYTES>>>(llm, Wo, bo, bl, out);
}